// round 8
// baseline (speedup 1.0000x reference)
#include <cuda_runtime.h>
#include <cstddef>

#define NB   8
#define NQ   100
#define SH   128
#define SW   128
#define OH   512
#define OW   512
#define QPI  4            // queries per iteration
#define NIT  (NQ / QPI)   // 25

__device__ __forceinline__ float fast_tanh(float x) {
    float r;
    asm("tanh.approx.f32 %0, %1;" : "=f"(r) : "f"(x));
    return r;
}

// Grid: (128 row-blocks k, 8 batches). Block: 512 threads, 3 CTAs/SM.
// Quad-query software pipeline, ONE __syncthreads per iteration:
//   iter j: horizontal(quad j, vrow[j&1]) || vertical(quad j+1 -> vrow[(j+1)&1])
//           || stage(quad j+2 -> buf[j&1])
// Data pre-halved at staging; weights pre-halved; +Sum(w/2) folded at the end.
__global__ __launch_bounds__(512, 3)
void m2f_fused_kernel(const float* __restrict__ cls,
                      const float* __restrict__ masks,
                      float* __restrict__ out)
{
    const int k = blockIdx.x;
    const int b = blockIdx.y;
    const int t = threadIdx.x;

    __shared__ __align__(16) float buf[2][QPI][3][SW];    // staged source rows (halved)
    __shared__ __align__(16) float vrow[2][QPI][4][SW];   // vertical lerps (halved)
    __shared__ float2 wts[NQ];
    __shared__ float2 wsum;

    // ---- per-CTA class softmax (halved) ----
    if (t < NQ) {
        const float* p = cls + ((size_t)b * NQ + t) * 3;
        float x0 = p[0], x1 = p[1], x2 = p[2];
        float m  = fmaxf(x0, fmaxf(x1, x2));
        float e0 = __expf(x0 - m), e1 = __expf(x1 - m), e2 = __expf(x2 - m);
        float inv = 0.5f / (e0 + e1 + e2);
        wts[t] = make_float2(e0 * inv, e1 * inv);
    }

    // clamped source rows
    const int r0 = (k == 0)      ? 0        : (k - 1);
    const int r2 = (k == SH - 1) ? (SH - 1) : (k + 1);
    const float* mb = masks + (size_t)b * NQ * SH * SW;
    const size_t qstride = (size_t)SH * SW;

    // staging role: 384 threads, one float4 each -> 4 queries x 3 rows x 128 floats
    const bool stager = (t < 384);
    const int  g  = t >> 5;            // warp id 0..15
    const int  sq = g / 3;             // query within quad (0..3) for stagers
    const int  rr = g % 3;             // row 0..2
    const int  c4 = t & 31;            // float4 index
    const int  stg_row = (rr == 0) ? r0 : ((rr == 1) ? k : r2);
    const float4* pf = reinterpret_cast<const float4*>(
        mb + (size_t)sq * qstride + (size_t)stg_row * SW) + c4;
    const size_t step = qstride;       // 4*qstride floats == qstride float4s

    // vertical role: vp = t>>7, vcol = t&127
    const int vp   = t >> 7;
    const int vcol = t & 127;
    const int ra   = (vp < 2) ? 0 : 1;
    const int rb   = ra + 1;
    const float vf = (vp == 0) ? 0.625f : (vp == 1) ? 0.875f
                   : (vp == 2) ? 0.125f : 0.375f;

    // horizontal role: kx = t&127, row-phase ph = t>>7
    const int kx  = t & 127;
    const int ph  = t >> 7;
    const int kxm = (kx == 0)      ? 0        : kx - 1;
    const int kxp = (kx == SW - 1) ? (SW - 1) : kx + 1;

    // ---- prologue: stage quad 0 ----
    if (stager) {
        float4 v = __ldg(pf);
        v.x *= 0.5f; v.y *= 0.5f; v.z *= 0.5f; v.w *= 0.5f;
        reinterpret_cast<float4*>(&buf[0][sq][rr][0])[c4] = v;
        pf += step;
    }
    __syncthreads();   // wts + buf[0] visible

    // weight sum (halved) by warp 0 — overlaps with prologue vertical below
    if (t < 32) {
        float sx = 0.f, sy = 0.f;
        for (int q = t; q < NQ; q += 32) { sx += wts[q].x; sy += wts[q].y; }
        #pragma unroll
        for (int o = 16; o > 0; o >>= 1) {
            sx += __shfl_down_sync(0xFFFFFFFFu, sx, o);
            sy += __shfl_down_sync(0xFFFFFFFFu, sy, o);
        }
        if (t == 0) wsum = make_float2(sx, sy);
    }

    // ---- prologue: vertical quad 0 -> vrow[0]; stage quad 1 -> buf[1] ----
    {
        float4 v;
        if (stager) v = __ldg(pf);
        #pragma unroll
        for (int e = 0; e < QPI; e++) {
            float a  = buf[0][e][ra][vcol];
            float bb = buf[0][e][rb][vcol];
            vrow[0][e][vp][vcol] = fmaf(vf, bb - a, a);
        }
        if (stager) {
            v.x *= 0.5f; v.y *= 0.5f; v.z *= 0.5f; v.w *= 0.5f;
            reinterpret_cast<float4*>(&buf[1][sq][rr][0])[c4] = v;
            pf += step;
        }
    }
    __syncthreads();

    float acc0[4] = {0.f,0.f,0.f,0.f};
    float acc1[4] = {0.f,0.f,0.f,0.f};

    #pragma unroll 1
    for (int j = 0; j < NIT; j++) {
        const int bs = j & 1;
        const int nb = bs ^ 1;

        // prefetch quad j+2
        float4 vn;
        const bool ds = stager && (j + 2 < NIT);
        if (ds) vn = __ldg(pf);

        // vertical: quad j+1 -> vrow[nb]  (reads buf[nb], staged 2 iters ago)
        if (j + 1 < NIT) {
            #pragma unroll
            for (int e = 0; e < QPI; e++) {
                float a  = buf[nb][e][ra][vcol];
                float bb = buf[nb][e][rb][vcol];
                vrow[nb][e][vp][vcol] = fmaf(vf, bb - a, a);
            }
        }

        // horizontal: quad j from vrow[bs]
        #pragma unroll
        for (int e = 0; e < QPI; e++) {
            const float2 w  = wts[QPI * j + e];
            const float  vL = vrow[bs][e][ph][kxm];
            const float  vM = vrow[bs][e][ph][kx];
            const float  vR = vrow[bs][e][ph][kxp];
            const float  dl = vM - vL;
            const float  dr = vR - vM;

            float t0 = fast_tanh(fmaf(0.625f, dl, vL));
            float t1 = fast_tanh(fmaf(0.875f, dl, vL));
            float t2 = fast_tanh(fmaf(0.125f, dr, vM));
            float t3 = fast_tanh(fmaf(0.375f, dr, vM));

            acc0[0] = fmaf(w.x, t0, acc0[0]);
            acc0[1] = fmaf(w.x, t1, acc0[1]);
            acc0[2] = fmaf(w.x, t2, acc0[2]);
            acc0[3] = fmaf(w.x, t3, acc0[3]);
            acc1[0] = fmaf(w.y, t0, acc1[0]);
            acc1[1] = fmaf(w.y, t1, acc1[1]);
            acc1[2] = fmaf(w.y, t2, acc1[2]);
            acc1[3] = fmaf(w.y, t3, acc1[3]);
        }

        // stage quad j+2 -> buf[bs] (quad j's slot; its last read was iter j-1)
        if (ds) {
            vn.x *= 0.5f; vn.y *= 0.5f; vn.z *= 0.5f; vn.w *= 0.5f;
            reinterpret_cast<float4*>(&buf[bs][sq][rr][0])[c4] = vn;
            pf += step;
        }
        __syncthreads();
    }

    // out[b][c][4k+ph][4kx + 0..3] = acc + Sum(w/2)
    const float2 S = wsum;
    const int y = 4 * k + ph;
    float4 o0 = make_float4(acc0[0] + S.x, acc0[1] + S.x,
                            acc0[2] + S.x, acc0[3] + S.x);
    float4 o1 = make_float4(acc1[0] + S.y, acc1[1] + S.y,
                            acc1[2] + S.y, acc1[3] + S.y);
    const size_t base0 = (((size_t)b * 2 + 0) * OH + y) * OW + 4 * kx;
    const size_t base1 = (((size_t)b * 2 + 1) * OH + y) * OW + 4 * kx;
    *reinterpret_cast<float4*>(out + base0) = o0;
    *reinterpret_cast<float4*>(out + base1) = o1;
}

extern "C" void kernel_launch(void* const* d_in, const int* in_sizes, int n_in,
                              void* d_out, int out_size)
{
    const float* cls   = (const float*)d_in[0];  // [8,100,3]
    const float* masks = (const float*)d_in[1];  // [8,100,128,128]
    float*       out   = (float*)d_out;          // [8,2,512,512]

    dim3 grid(SH, NB);
    dim3 block(512);
    m2f_fused_kernel<<<grid, block>>>(cls, masks, out);
}

// round 9
// speedup vs baseline: 1.0031x; 1.0031x over previous
#include <cuda_runtime.h>
#include <cstddef>

#define NB   8
#define NQ   100
#define SH   128
#define SW   128
#define OH   512
#define OW   512
#define QPI  4            // queries per iteration
#define NIT  (NQ / QPI)   // 25

__device__ __forceinline__ float fast_tanh(float x) {
    float r;
    asm("tanh.approx.f32 %0, %1;" : "=f"(r) : "f"(x));
    return r;
}

// Grid: (128 row-blocks k, 8 batches). Block: 512 threads, 3 CTAs/SM.
// Quad-query software pipeline, ONE __syncthreads per iteration:
//   iter j: horizontal(quad j, vrow[j&1]) || vertical(quad j+1 -> vrow[(j+1)&1])
//           || stage(quad j+2 -> buf[j&1])
// Data pre-halved at staging; weights pre-halved; +Sum(w/2) folded at the end.
__global__ __launch_bounds__(512, 3)
void m2f_fused_kernel(const float* __restrict__ cls,
                      const float* __restrict__ masks,
                      float* __restrict__ out)
{
    const int k = blockIdx.x;
    const int b = blockIdx.y;
    const int t = threadIdx.x;

    __shared__ __align__(16) float buf[2][QPI][3][SW];    // staged source rows (halved)
    __shared__ __align__(16) float vrow[2][QPI][4][SW];   // vertical lerps (halved)
    __shared__ float2 wts[NQ];
    __shared__ float2 wsum;

    // ---- per-CTA class softmax (halved) ----
    if (t < NQ) {
        const float* p = cls + ((size_t)b * NQ + t) * 3;
        float x0 = p[0], x1 = p[1], x2 = p[2];
        float m  = fmaxf(x0, fmaxf(x1, x2));
        float e0 = __expf(x0 - m), e1 = __expf(x1 - m), e2 = __expf(x2 - m);
        float inv = 0.5f / (e0 + e1 + e2);
        wts[t] = make_float2(e0 * inv, e1 * inv);
    }

    // clamped source rows
    const int r0 = (k == 0)      ? 0        : (k - 1);
    const int r2 = (k == SH - 1) ? (SH - 1) : (k + 1);
    const float* mb = masks + (size_t)b * NQ * SH * SW;
    const size_t qstride = (size_t)SH * SW;

    // staging role: 384 threads, one float4 each -> 4 queries x 3 rows x 128 floats
    const bool stager = (t < 384);
    const int  g  = t >> 5;            // warp id 0..15
    const int  sq = g / 3;             // query within quad (0..3) for stagers
    const int  rr = g % 3;             // row 0..2
    const int  c4 = t & 31;            // float4 index
    const int  stg_row = (rr == 0) ? r0 : ((rr == 1) ? k : r2);
    const float4* pf = reinterpret_cast<const float4*>(
        mb + (size_t)sq * qstride + (size_t)stg_row * SW) + c4;
    const size_t step = qstride;       // 4*qstride floats == qstride float4s

    // vertical role: vp = t>>7, vcol = t&127
    const int vp   = t >> 7;
    const int vcol = t & 127;
    const int ra   = (vp < 2) ? 0 : 1;
    const int rb   = ra + 1;
    const float vf = (vp == 0) ? 0.625f : (vp == 1) ? 0.875f
                   : (vp == 2) ? 0.125f : 0.375f;

    // horizontal role: kx = t&127, row-phase ph = t>>7
    const int kx  = t & 127;
    const int ph  = t >> 7;
    const int kxm = (kx == 0)      ? 0        : kx - 1;
    const int kxp = (kx == SW - 1) ? (SW - 1) : kx + 1;

    // ---- prologue: stage quad 0 ----
    if (stager) {
        float4 v = __ldg(pf);
        v.x *= 0.5f; v.y *= 0.5f; v.z *= 0.5f; v.w *= 0.5f;
        reinterpret_cast<float4*>(&buf[0][sq][rr][0])[c4] = v;
        pf += step;
    }
    __syncthreads();   // wts + buf[0] visible

    // weight sum (halved) by warp 0 — overlaps with prologue vertical below
    if (t < 32) {
        float sx = 0.f, sy = 0.f;
        for (int q = t; q < NQ; q += 32) { sx += wts[q].x; sy += wts[q].y; }
        #pragma unroll
        for (int o = 16; o > 0; o >>= 1) {
            sx += __shfl_down_sync(0xFFFFFFFFu, sx, o);
            sy += __shfl_down_sync(0xFFFFFFFFu, sy, o);
        }
        if (t == 0) wsum = make_float2(sx, sy);
    }

    // ---- prologue: vertical quad 0 -> vrow[0]; stage quad 1 -> buf[1] ----
    {
        float4 v;
        if (stager) v = __ldg(pf);
        #pragma unroll
        for (int e = 0; e < QPI; e++) {
            float a  = buf[0][e][ra][vcol];
            float bb = buf[0][e][rb][vcol];
            vrow[0][e][vp][vcol] = fmaf(vf, bb - a, a);
        }
        if (stager) {
            v.x *= 0.5f; v.y *= 0.5f; v.z *= 0.5f; v.w *= 0.5f;
            reinterpret_cast<float4*>(&buf[1][sq][rr][0])[c4] = v;
            pf += step;
        }
    }
    __syncthreads();

    float acc0[4] = {0.f,0.f,0.f,0.f};
    float acc1[4] = {0.f,0.f,0.f,0.f};

    #pragma unroll 1
    for (int j = 0; j < NIT; j++) {
        const int bs = j & 1;
        const int nb = bs ^ 1;

        // prefetch quad j+2
        float4 vn;
        const bool ds = stager && (j + 2 < NIT);
        if (ds) vn = __ldg(pf);

        // vertical: quad j+1 -> vrow[nb]  (reads buf[nb], staged 2 iters ago)
        if (j + 1 < NIT) {
            #pragma unroll
            for (int e = 0; e < QPI; e++) {
                float a  = buf[nb][e][ra][vcol];
                float bb = buf[nb][e][rb][vcol];
                vrow[nb][e][vp][vcol] = fmaf(vf, bb - a, a);
            }
        }

        // horizontal: quad j from vrow[bs]
        #pragma unroll
        for (int e = 0; e < QPI; e++) {
            const float2 w  = wts[QPI * j + e];
            const float  vL = vrow[bs][e][ph][kxm];
            const float  vM = vrow[bs][e][ph][kx];
            const float  vR = vrow[bs][e][ph][kxp];
            const float  dl = vM - vL;
            const float  dr = vR - vM;

            float t0 = fast_tanh(fmaf(0.625f, dl, vL));
            float t1 = fast_tanh(fmaf(0.875f, dl, vL));
            float t2 = fast_tanh(fmaf(0.125f, dr, vM));
            float t3 = fast_tanh(fmaf(0.375f, dr, vM));

            acc0[0] = fmaf(w.x, t0, acc0[0]);
            acc0[1] = fmaf(w.x, t1, acc0[1]);
            acc0[2] = fmaf(w.x, t2, acc0[2]);
            acc0[3] = fmaf(w.x, t3, acc0[3]);
            acc1[0] = fmaf(w.y, t0, acc1[0]);
            acc1[1] = fmaf(w.y, t1, acc1[1]);
            acc1[2] = fmaf(w.y, t2, acc1[2]);
            acc1[3] = fmaf(w.y, t3, acc1[3]);
        }

        // stage quad j+2 -> buf[bs] (quad j's slot; its last read was iter j-1)
        if (ds) {
            vn.x *= 0.5f; vn.y *= 0.5f; vn.z *= 0.5f; vn.w *= 0.5f;
            reinterpret_cast<float4*>(&buf[bs][sq][rr][0])[c4] = vn;
            pf += step;
        }
        __syncthreads();
    }

    // out[b][c][4k+ph][4kx + 0..3] = acc + Sum(w/2)
    const float2 S = wsum;
    const int y = 4 * k + ph;
    float4 o0 = make_float4(acc0[0] + S.x, acc0[1] + S.x,
                            acc0[2] + S.x, acc0[3] + S.x);
    float4 o1 = make_float4(acc1[0] + S.y, acc1[1] + S.y,
                            acc1[2] + S.y, acc1[3] + S.y);
    const size_t base0 = (((size_t)b * 2 + 0) * OH + y) * OW + 4 * kx;
    const size_t base1 = (((size_t)b * 2 + 1) * OH + y) * OW + 4 * kx;
    *reinterpret_cast<float4*>(out + base0) = o0;
    *reinterpret_cast<float4*>(out + base1) = o1;
}

extern "C" void kernel_launch(void* const* d_in, const int* in_sizes, int n_in,
                              void* d_out, int out_size)
{
    const float* cls   = (const float*)d_in[0];  // [8,100,3]
    const float* masks = (const float*)d_in[1];  // [8,100,128,128]
    float*       out   = (float*)d_out;          // [8,2,512,512]

    dim3 grid(SH, NB);
    dim3 block(512);
    m2f_fused_kernel<<<grid, block>>>(cls, masks, out);
}